// round 4
// baseline (speedup 1.0000x reference)
#include <cuda_runtime.h>
#include <cuda_bf16.h>

#define LRES 128
#define HRES 1024
#define NCH 8

// Channel-innermost scratch copies (allocation-free: __device__ globals).
__device__ float g_grid_t[LRES * LRES * LRES * NCH];        // [z][y][x][c]  64 MB
__device__ float g_planes_t[3 * HRES * HRES * NCH];         // [p][h][w][c]  96 MB

// ---------------------------------------------------------------------------
// Transpose [C, D, H, W] -> [D, H, W, C].
// Reads coalesced (lanes stride spatial, fixed c), writes 32B-contiguous/thread.
// ---------------------------------------------------------------------------
__global__ void transpose_grid_kernel(const float* __restrict__ in) {
    const int V = LRES * LRES * LRES;
    int v = blockIdx.x * blockDim.x + threadIdx.x;
    if (v >= V) return;
    float4 a, b;
    a.x = __ldg(in + 0 * V + v);
    a.y = __ldg(in + 1 * V + v);
    a.z = __ldg(in + 2 * V + v);
    a.w = __ldg(in + 3 * V + v);
    b.x = __ldg(in + 4 * V + v);
    b.y = __ldg(in + 5 * V + v);
    b.z = __ldg(in + 6 * V + v);
    b.w = __ldg(in + 7 * V + v);
    float4* out = reinterpret_cast<float4*>(g_grid_t) + (size_t)v * 2;
    out[0] = a;
    out[1] = b;
}

// Transpose [3, C, H, W] -> [3][H][W][C].
__global__ void transpose_planes_kernel(const float* __restrict__ in) {
    const int V2 = HRES * HRES;
    int t = blockIdx.x * blockDim.x + threadIdx.x;
    if (t >= 3 * V2) return;
    int p = t / V2;
    int v = t - p * V2;
    const float* base = in + (size_t)p * NCH * V2 + v;
    float4 a, b;
    a.x = __ldg(base + 0 * V2);
    a.y = __ldg(base + 1 * V2);
    a.z = __ldg(base + 2 * V2);
    a.w = __ldg(base + 3 * V2);
    b.x = __ldg(base + 4 * V2);
    b.y = __ldg(base + 5 * V2);
    b.z = __ldg(base + 6 * V2);
    b.w = __ldg(base + 7 * V2);
    float4* out = reinterpret_cast<float4*>(g_planes_t) + (size_t)t * 2;
    out[0] = a;
    out[1] = b;
}

// ---------------------------------------------------------------------------
// Gather: one thread per point.
// ---------------------------------------------------------------------------
__device__ __forceinline__ void to_idx(float c, int size, int& i0, int& i1, float& w) {
    // align_corners=True mapping; w computed from UNCLIPPED floor (matches ref).
    float p = (c + 1.0f) * 0.5f * (float)(size - 1);
    float f = floorf(p);
    w = p - f;
    int i = (int)f;
    i0 = min(max(i, 0), size - 1);
    i1 = min(i0 + 1, size - 1);
}

__global__ void __launch_bounds__(256) gather_kernel(
    const float* __restrict__ xyz,
    const int* __restrict__ bound_p,
    float* __restrict__ out,
    int N)
{
    int n = blockIdx.x * blockDim.x + threadIdx.x;
    if (n >= N) return;

    // bound: robust to int32 / int64-low-word / float32 encodings of a scalar.
    int bi = __ldg(bound_p);
    float bound = (bi > 0 && bi < 100000000) ? (float)bi : __int_as_float(bi);
    float inv = 1.0f / bound;

    float x = __ldg(xyz + 3 * n + 0) * inv;
    float y = __ldg(xyz + 3 * n + 1) * inv;
    float z = __ldg(xyz + 3 * n + 2) * inv;

    float acc[NCH];
#pragma unroll
    for (int c = 0; c < NCH; c++) acc[c] = 0.0f;

    const float4* GT = reinterpret_cast<const float4*>(g_grid_t);
    const float4* PT = reinterpret_cast<const float4*>(g_planes_t);

    // ---- trilinear grid sample ----
    {
        int x0, x1, y0, y1, z0, z1;
        float wx, wy, wz;
        to_idx(x, LRES, x0, x1, wx);
        to_idx(y, LRES, y0, y1, wy);
        to_idx(z, LRES, z0, z1, wz);

        auto addg = [&](int zz, int yy, int xx, float w) {
            int base = (((zz * LRES) + yy) * LRES + xx) * 2;  // float4 units
            float4 a = __ldg(GT + base);
            float4 b = __ldg(GT + base + 1);
            acc[0] += w * a.x; acc[1] += w * a.y; acc[2] += w * a.z; acc[3] += w * a.w;
            acc[4] += w * b.x; acc[5] += w * b.y; acc[6] += w * b.z; acc[7] += w * b.w;
        };
        float ux = 1.0f - wx, uy = 1.0f - wy, uz = 1.0f - wz;
        addg(z0, y0, x0, uz * uy * ux);
        addg(z0, y0, x1, uz * uy * wx);
        addg(z0, y1, x0, uz * wy * ux);
        addg(z0, y1, x1, uz * wy * wx);
        addg(z1, y0, x0, wz * uy * ux);
        addg(z1, y0, x1, wz * uy * wx);
        addg(z1, y1, x0, wz * wy * ux);
        addg(z1, y1, x1, wz * wy * wx);
    }

    // ---- tri-plane bilinear samples ----
    {
        int xh0, xh1, yh0, yh1, zh0, zh1;
        float wxh, wyh, wzh;
        to_idx(x, HRES, xh0, xh1, wxh);
        to_idx(y, HRES, yh0, yh1, wyh);
        to_idx(z, HRES, zh0, zh1, wzh);

        auto addp = [&](int plane, int hh, int ww, float w) {
            int base = (plane * (HRES * HRES) + hh * HRES + ww) * 2;  // float4 units
            float4 a = __ldg(PT + base);
            float4 b = __ldg(PT + base + 1);
            acc[0] += w * a.x; acc[1] += w * a.y; acc[2] += w * a.z; acc[3] += w * a.w;
            acc[4] += w * b.x; acc[5] += w * b.y; acc[6] += w * b.z; acc[7] += w * b.w;
        };

        // plane 0: coords (x -> W, y -> H)
        {
            float uw = 1.0f - wxh, uh = 1.0f - wyh;
            addp(0, yh0, xh0, uh * uw);
            addp(0, yh0, xh1, uh * wxh);
            addp(0, yh1, xh0, wyh * uw);
            addp(0, yh1, xh1, wyh * wxh);
        }
        // plane 1: coords (y -> W, z -> H)
        {
            float uw = 1.0f - wyh, uh = 1.0f - wzh;
            addp(1, zh0, yh0, uh * uw);
            addp(1, zh0, yh1, uh * wyh);
            addp(1, zh1, yh0, wzh * uw);
            addp(1, zh1, yh1, wzh * wyh);
        }
        // plane 2: coords (z -> W, x -> H)
        {
            float uw = 1.0f - wzh, uh = 1.0f - wxh;
            addp(2, xh0, zh0, uh * uw);
            addp(2, xh0, zh1, uh * wzh);
            addp(2, xh1, zh0, wxh * uw);
            addp(2, xh1, zh1, wxh * wzh);
        }
    }

    // ---- write [N, 8] output, 2 x STG.128 ----
    float4* out4 = reinterpret_cast<float4*>(out) + (size_t)n * 2;
    out4[0] = make_float4(acc[0], acc[1], acc[2], acc[3]);
    out4[1] = make_float4(acc[4], acc[5], acc[6], acc[7]);
}

extern "C" void kernel_launch(void* const* d_in, const int* in_sizes, int n_in,
                              void* d_out, int out_size) {
    const float* xyz   = (const float*)d_in[0];
    const int*   bound = (const int*)d_in[1];
    const float* Lg    = (const float*)d_in[2];
    const float* Hp    = (const float*)d_in[3];
    float* out = (float*)d_out;

    int N = in_sizes[0] / 3;

    const int VG = LRES * LRES * LRES;
    transpose_grid_kernel<<<(VG + 255) / 256, 256>>>(Lg);

    const int VP = 3 * HRES * HRES;
    transpose_planes_kernel<<<(VP + 255) / 256, 256>>>(Hp);

    gather_kernel<<<(N + 255) / 256, 256>>>(xyz, bound, out, N);
}

// round 5
// speedup vs baseline: 1.5472x; 1.5472x over previous
#include <cuda_runtime.h>
#include <cuda_fp16.h>
#include <cuda_bf16.h>

#define LRES 128
#define HRES 1024
#define NCH 8

// Channel-innermost fp16 scratch copies (allocation-free: __device__ globals).
// One texel = 8 halves = 16B = exactly one LDG.128.
__device__ __half g_grid_h[LRES * LRES * LRES * NCH];    // [z][y][x][c]  32 MB
__device__ __half g_planes_h[3 * HRES * HRES * NCH];     // [p][h][w][c]  48 MB

__device__ __forceinline__ uint4 pack8_half(float4 a, float4 b) {
    union { uint4 u; __half2 h[4]; } r;
    r.h[0] = __floats2half2_rn(a.x, a.y);
    r.h[1] = __floats2half2_rn(a.z, a.w);
    r.h[2] = __floats2half2_rn(b.x, b.y);
    r.h[3] = __floats2half2_rn(b.z, b.w);
    return r.u;
}

// ---------------------------------------------------------------------------
// Transpose [C, D, H, W] fp32 -> [D, H, W, C] fp16.
// Reads coalesced (lanes stride spatial, fixed c), one 16B write per thread.
// ---------------------------------------------------------------------------
__global__ void transpose_grid_kernel(const float* __restrict__ in) {
    const int V = LRES * LRES * LRES;
    int v = blockIdx.x * blockDim.x + threadIdx.x;
    if (v >= V) return;
    float4 a, b;
    a.x = __ldg(in + 0 * V + v);
    a.y = __ldg(in + 1 * V + v);
    a.z = __ldg(in + 2 * V + v);
    a.w = __ldg(in + 3 * V + v);
    b.x = __ldg(in + 4 * V + v);
    b.y = __ldg(in + 5 * V + v);
    b.z = __ldg(in + 6 * V + v);
    b.w = __ldg(in + 7 * V + v);
    reinterpret_cast<uint4*>(g_grid_h)[v] = pack8_half(a, b);
}

// Transpose [3, C, H, W] fp32 -> [3][H][W][C] fp16.
__global__ void transpose_planes_kernel(const float* __restrict__ in) {
    const int V2 = HRES * HRES;
    int t = blockIdx.x * blockDim.x + threadIdx.x;
    if (t >= 3 * V2) return;
    int p = t / V2;
    int v = t - p * V2;
    const float* base = in + (size_t)p * NCH * V2 + v;
    float4 a, b;
    a.x = __ldg(base + 0 * V2);
    a.y = __ldg(base + 1 * V2);
    a.z = __ldg(base + 2 * V2);
    a.w = __ldg(base + 3 * V2);
    b.x = __ldg(base + 4 * V2);
    b.y = __ldg(base + 5 * V2);
    b.z = __ldg(base + 6 * V2);
    b.w = __ldg(base + 7 * V2);
    reinterpret_cast<uint4*>(g_planes_h)[t] = pack8_half(a, b);
}

// ---------------------------------------------------------------------------
// Gather: one thread per point. 20 x LDG.128 scattered, fp32 accumulate.
// ---------------------------------------------------------------------------
__device__ __forceinline__ void to_idx(float c, int size, int& i0, int& i1, float& w) {
    // align_corners=True mapping; w computed from UNCLIPPED floor (matches ref).
    float p = (c + 1.0f) * 0.5f * (float)(size - 1);
    float f = floorf(p);
    w = p - f;
    int i = (int)f;
    i0 = min(max(i, 0), size - 1);
    i1 = min(i0 + 1, size - 1);
}

__device__ __forceinline__ void acc_texel(float* acc, uint4 v, float w) {
    union { uint4 u; __half2 h[4]; } r; r.u = v;
    float2 f0 = __half22float2(r.h[0]);
    float2 f1 = __half22float2(r.h[1]);
    float2 f2 = __half22float2(r.h[2]);
    float2 f3 = __half22float2(r.h[3]);
    acc[0] = fmaf(w, f0.x, acc[0]); acc[1] = fmaf(w, f0.y, acc[1]);
    acc[2] = fmaf(w, f1.x, acc[2]); acc[3] = fmaf(w, f1.y, acc[3]);
    acc[4] = fmaf(w, f2.x, acc[4]); acc[5] = fmaf(w, f2.y, acc[5]);
    acc[6] = fmaf(w, f3.x, acc[6]); acc[7] = fmaf(w, f3.y, acc[7]);
}

__global__ void __launch_bounds__(256) gather_kernel(
    const float* __restrict__ xyz,
    const int* __restrict__ bound_p,
    float* __restrict__ out,
    int N)
{
    int n = blockIdx.x * blockDim.x + threadIdx.x;
    if (n >= N) return;

    // bound: robust to int32 / float32 encodings of a scalar.
    int bi = __ldg(bound_p);
    float bound = (bi > 0 && bi < 100000000) ? (float)bi : __int_as_float(bi);
    float inv = 1.0f / bound;

    float x = __ldg(xyz + 3 * n + 0) * inv;
    float y = __ldg(xyz + 3 * n + 1) * inv;
    float z = __ldg(xyz + 3 * n + 2) * inv;

    const uint4* GT = reinterpret_cast<const uint4*>(g_grid_h);
    const uint4* PT = reinterpret_cast<const uint4*>(g_planes_h);

    // ---- index math up front ----
    int x0, x1, y0, y1, z0, z1;
    float wx, wy, wz;
    to_idx(x, LRES, x0, x1, wx);
    to_idx(y, LRES, y0, y1, wy);
    to_idx(z, LRES, z0, z1, wz);

    int xh0, xh1, yh0, yh1, zh0, zh1;
    float wxh, wyh, wzh;
    to_idx(x, HRES, xh0, xh1, wxh);
    to_idx(y, HRES, yh0, yh1, wyh);
    to_idx(z, HRES, zh0, zh1, wzh);

    // ---- issue all 20 loads (compiler batches for MLP) ----
    #define GIDX(zz, yy, xx) (((zz) * LRES + (yy)) * LRES + (xx))
    uint4 g000 = __ldg(GT + GIDX(z0, y0, x0));
    uint4 g001 = __ldg(GT + GIDX(z0, y0, x1));
    uint4 g010 = __ldg(GT + GIDX(z0, y1, x0));
    uint4 g011 = __ldg(GT + GIDX(z0, y1, x1));
    uint4 g100 = __ldg(GT + GIDX(z1, y0, x0));
    uint4 g101 = __ldg(GT + GIDX(z1, y0, x1));
    uint4 g110 = __ldg(GT + GIDX(z1, y1, x0));
    uint4 g111 = __ldg(GT + GIDX(z1, y1, x1));
    #undef GIDX

    #define PIDX(p, hh, ww) ((p) * (HRES * HRES) + (hh) * HRES + (ww))
    uint4 p0a = __ldg(PT + PIDX(0, yh0, xh0));
    uint4 p0b = __ldg(PT + PIDX(0, yh0, xh1));
    uint4 p0c = __ldg(PT + PIDX(0, yh1, xh0));
    uint4 p0d = __ldg(PT + PIDX(0, yh1, xh1));
    uint4 p1a = __ldg(PT + PIDX(1, zh0, yh0));
    uint4 p1b = __ldg(PT + PIDX(1, zh0, yh1));
    uint4 p1c = __ldg(PT + PIDX(1, zh1, yh0));
    uint4 p1d = __ldg(PT + PIDX(1, zh1, yh1));
    uint4 p2a = __ldg(PT + PIDX(2, xh0, zh0));
    uint4 p2b = __ldg(PT + PIDX(2, xh0, zh1));
    uint4 p2c = __ldg(PT + PIDX(2, xh1, zh0));
    uint4 p2d = __ldg(PT + PIDX(2, xh1, zh1));
    #undef PIDX

    // ---- accumulate fp32 ----
    float acc[NCH];
#pragma unroll
    for (int c = 0; c < NCH; c++) acc[c] = 0.0f;

    {
        float ux = 1.0f - wx, uy = 1.0f - wy, uz = 1.0f - wz;
        acc_texel(acc, g000, uz * uy * ux);
        acc_texel(acc, g001, uz * uy * wx);
        acc_texel(acc, g010, uz * wy * ux);
        acc_texel(acc, g011, uz * wy * wx);
        acc_texel(acc, g100, wz * uy * ux);
        acc_texel(acc, g101, wz * uy * wx);
        acc_texel(acc, g110, wz * wy * ux);
        acc_texel(acc, g111, wz * wy * wx);
    }
    {
        float uw = 1.0f - wxh, uh = 1.0f - wyh;   // plane 0: (x->W, y->H)
        acc_texel(acc, p0a, uh * uw);
        acc_texel(acc, p0b, uh * wxh);
        acc_texel(acc, p0c, wyh * uw);
        acc_texel(acc, p0d, wyh * wxh);
    }
    {
        float uw = 1.0f - wyh, uh = 1.0f - wzh;   // plane 1: (y->W, z->H)
        acc_texel(acc, p1a, uh * uw);
        acc_texel(acc, p1b, uh * wyh);
        acc_texel(acc, p1c, wzh * uw);
        acc_texel(acc, p1d, wzh * wyh);
    }
    {
        float uw = 1.0f - wzh, uh = 1.0f - wxh;   // plane 2: (z->W, x->H)
        acc_texel(acc, p2a, uh * uw);
        acc_texel(acc, p2b, uh * wzh);
        acc_texel(acc, p2c, wxh * uw);
        acc_texel(acc, p2d, wxh * wzh);
    }

    // ---- write [N, 8] output, 2 x STG.128 ----
    float4* out4 = reinterpret_cast<float4*>(out) + (size_t)n * 2;
    out4[0] = make_float4(acc[0], acc[1], acc[2], acc[3]);
    out4[1] = make_float4(acc[4], acc[5], acc[6], acc[7]);
}

extern "C" void kernel_launch(void* const* d_in, const int* in_sizes, int n_in,
                              void* d_out, int out_size) {
    const float* xyz   = (const float*)d_in[0];
    const int*   bound = (const int*)d_in[1];
    const float* Lg    = (const float*)d_in[2];
    const float* Hp    = (const float*)d_in[3];
    float* out = (float*)d_out;

    int N = in_sizes[0] / 3;

    const int VG = LRES * LRES * LRES;
    transpose_grid_kernel<<<(VG + 255) / 256, 256>>>(Lg);

    const int VP = 3 * HRES * HRES;
    transpose_planes_kernel<<<(VP + 255) / 256, 256>>>(Hp);

    gather_kernel<<<(N + 255) / 256, 256>>>(xyz, bound, out, N);
}

// round 6
// speedup vs baseline: 2.0181x; 1.3043x over previous
#include <cuda_runtime.h>
#include <cuda_fp16.h>
#include <cuda_bf16.h>

#define LRES 128
#define HRES 1024
#define NCH 8

// Channel-innermost fp16 scratch copies (allocation-free: __device__ globals).
// One texel = 8 halves = 16B = exactly one LDG.128.
__device__ __half g_grid_h[LRES * LRES * LRES * NCH];    // [z][y][x][c]  32 MB
__device__ __half g_planes_h[3 * HRES * HRES * NCH];     // [p][h][w][c]  48 MB

__device__ __forceinline__ uint4 pack8_half(float4 a, float4 b) {
    union { uint4 u; __half2 h[4]; } r;
    r.h[0] = __floats2half2_rn(a.x, a.y);
    r.h[1] = __floats2half2_rn(a.z, a.w);
    r.h[2] = __floats2half2_rn(b.x, b.y);
    r.h[3] = __floats2half2_rn(b.z, b.w);
    return r.u;
}

// ---------------------------------------------------------------------------
// Transpose [C, D, H, W] fp32 -> [D, H, W, C] fp16. 4 texels per thread.
// ---------------------------------------------------------------------------
__global__ void transpose_grid_kernel(const float* __restrict__ in) {
    const int V = LRES * LRES * LRES;
    int t = blockIdx.x * blockDim.x + threadIdx.x;
    int v = t * 4;
    if (v >= V) return;
    float4 row[NCH];
#pragma unroll
    for (int c = 0; c < NCH; c++)
        row[c] = __ldg(reinterpret_cast<const float4*>(in + (size_t)c * V + v));
    uint4* out = reinterpret_cast<uint4*>(g_grid_h) + v;
#pragma unroll
    for (int j = 0; j < 4; j++) {
        float4 a, b;
        const float* rj = &row[0].x;  // not used; explicit gather below
        a.x = (&row[0].x)[j]; a.y = (&row[1].x)[j]; a.z = (&row[2].x)[j]; a.w = (&row[3].x)[j];
        b.x = (&row[4].x)[j]; b.y = (&row[5].x)[j]; b.z = (&row[6].x)[j]; b.w = (&row[7].x)[j];
        out[j] = pack8_half(a, b);
    }
}

// Transpose [3, C, H, W] fp32 -> [3][H][W][C] fp16. 4 texels per thread.
__global__ void transpose_planes_kernel(const float* __restrict__ in) {
    const int V2 = HRES * HRES;
    int t = blockIdx.x * blockDim.x + threadIdx.x;
    int tv = t * 4;
    if (tv >= 3 * V2) return;
    int p = tv / V2;             // V2 divisible by 4, so all 4 texels same plane
    int v = tv - p * V2;
    const float* base = in + (size_t)p * NCH * V2 + v;
    float4 row[NCH];
#pragma unroll
    for (int c = 0; c < NCH; c++)
        row[c] = __ldg(reinterpret_cast<const float4*>(base + (size_t)c * V2));
    uint4* out = reinterpret_cast<uint4*>(g_planes_h) + tv;
#pragma unroll
    for (int j = 0; j < 4; j++) {
        float4 a, b;
        a.x = (&row[0].x)[j]; a.y = (&row[1].x)[j]; a.z = (&row[2].x)[j]; a.w = (&row[3].x)[j];
        b.x = (&row[4].x)[j]; b.y = (&row[5].x)[j]; b.z = (&row[6].x)[j]; b.w = (&row[7].x)[j];
        out[j] = pack8_half(a, b);
    }
}

// ---------------------------------------------------------------------------
// Pair-lane gather: lanes (2i, 2i+1) share point i; lane r handles the
// W-dimension index x_r of every sample pair. 10 LDG.128 per lane,
// pair-reduce via SHFL.BFLY, contiguous 16B store per lane.
// ---------------------------------------------------------------------------
__device__ __forceinline__ void to_idx(float c, int size, int& i0, int& i1, float& w) {
    // align_corners=True mapping; w from UNCLIPPED floor (matches ref).
    float p = (c + 1.0f) * 0.5f * (float)(size - 1);
    float f = floorf(p);
    w = p - f;
    int i = (int)f;
    i0 = min(max(i, 0), size - 1);
    i1 = min(i0 + 1, size - 1);
}

__device__ __forceinline__ void acc_texel(float* acc, uint4 v, float w) {
    union { uint4 u; __half2 h[4]; } r; r.u = v;
    float2 f0 = __half22float2(r.h[0]);
    float2 f1 = __half22float2(r.h[1]);
    float2 f2 = __half22float2(r.h[2]);
    float2 f3 = __half22float2(r.h[3]);
    acc[0] = fmaf(w, f0.x, acc[0]); acc[1] = fmaf(w, f0.y, acc[1]);
    acc[2] = fmaf(w, f1.x, acc[2]); acc[3] = fmaf(w, f1.y, acc[3]);
    acc[4] = fmaf(w, f2.x, acc[4]); acc[5] = fmaf(w, f2.y, acc[5]);
    acc[6] = fmaf(w, f3.x, acc[6]); acc[7] = fmaf(w, f3.y, acc[7]);
}

__global__ void __launch_bounds__(256) gather_kernel(
    const float* __restrict__ xyz,
    const int* __restrict__ bound_p,
    float* __restrict__ out,
    int N)
{
    int tid = blockIdx.x * blockDim.x + threadIdx.x;
    int n = tid >> 1;            // point index (2 lanes per point)
    int r = tid & 1;             // 0: low W index, 1: high W index
    if (n >= N) return;          // pairs drop together; warp stays pair-aligned

    int bi = __ldg(bound_p);
    float bound = (bi > 0 && bi < 100000000) ? (float)bi : __int_as_float(bi);
    float inv = 1.0f / bound;

    float x = __ldg(xyz + 3 * n + 0) * inv;
    float y = __ldg(xyz + 3 * n + 1) * inv;
    float z = __ldg(xyz + 3 * n + 2) * inv;

    const uint4* GT = reinterpret_cast<const uint4*>(g_grid_h);
    const uint4* PT = reinterpret_cast<const uint4*>(g_planes_h);

    // ---- index math (both lanes compute identically) ----
    int x0, x1, y0, y1, z0, z1;
    float wx, wy, wz;
    to_idx(x, LRES, x0, x1, wx);
    to_idx(y, LRES, y0, y1, wy);
    to_idx(z, LRES, z0, z1, wz);

    int xh0, xh1, yh0, yh1, zh0, zh1;
    float wxh, wyh, wzh;
    to_idx(x, HRES, xh0, xh1, wxh);
    to_idx(y, HRES, yh0, yh1, wyh);
    to_idx(z, HRES, zh0, zh1, wzh);

    // lane-specific W-dim picks + weights
    int   gx  = r ? x1  : x0;   float wgx = r ? wx  : 1.0f - wx;
    int   p0x = r ? xh1 : xh0;  float w0x = r ? wxh : 1.0f - wxh;  // plane0 W = x
    int   p1y = r ? yh1 : yh0;  float w1y = r ? wyh : 1.0f - wyh;  // plane1 W = y
    int   p2z = r ? zh1 : zh0;  float w2z = r ? wzh : 1.0f - wzh;  // plane2 W = z

    // ---- 10 loads, batched for MLP ----
    #define GIDX(zz, yy) (((zz) * LRES + (yy)) * LRES + gx)
    uint4 g00 = __ldg(GT + GIDX(z0, y0));
    uint4 g01 = __ldg(GT + GIDX(z0, y1));
    uint4 g10 = __ldg(GT + GIDX(z1, y0));
    uint4 g11 = __ldg(GT + GIDX(z1, y1));
    #undef GIDX
    #define PIDX(p, hh, ww) ((p) * (HRES * HRES) + (hh) * HRES + (ww))
    uint4 pa0 = __ldg(PT + PIDX(0, yh0, p0x));
    uint4 pa1 = __ldg(PT + PIDX(0, yh1, p0x));
    uint4 pb0 = __ldg(PT + PIDX(1, zh0, p1y));
    uint4 pb1 = __ldg(PT + PIDX(1, zh1, p1y));
    uint4 pc0 = __ldg(PT + PIDX(2, xh0, p2z));
    uint4 pc1 = __ldg(PT + PIDX(2, xh1, p2z));
    #undef PIDX

    // ---- accumulate fp32 (half the corners; pair sum completes it) ----
    float acc[NCH];
#pragma unroll
    for (int c = 0; c < NCH; c++) acc[c] = 0.0f;

    {
        float uy = 1.0f - wy, uz = 1.0f - wz;
        acc_texel(acc, g00, uz * uy * wgx);
        acc_texel(acc, g01, uz * wy * wgx);
        acc_texel(acc, g10, wz * uy * wgx);
        acc_texel(acc, g11, wz * wy * wgx);
    }
    acc_texel(acc, pa0, (1.0f - wyh) * w0x);   // plane0: H = y
    acc_texel(acc, pa1, wyh * w0x);
    acc_texel(acc, pb0, (1.0f - wzh) * w1y);   // plane1: H = z
    acc_texel(acc, pb1, wzh * w1y);
    acc_texel(acc, pc0, (1.0f - wxh) * w2z);   // plane2: H = x
    acc_texel(acc, pc1, wxh * w2z);

    // ---- pair reduction: both lanes end with the full 8-channel sum ----
    unsigned mask = __activemask();
#pragma unroll
    for (int c = 0; c < NCH; c++)
        acc[c] += __shfl_xor_sync(mask, acc[c], 1);

    // ---- store: lane r writes float4 #r of point n -> fully contiguous ----
    float4 v = r ? make_float4(acc[4], acc[5], acc[6], acc[7])
                 : make_float4(acc[0], acc[1], acc[2], acc[3]);
    reinterpret_cast<float4*>(out)[(size_t)n * 2 + r] = v;
}

extern "C" void kernel_launch(void* const* d_in, const int* in_sizes, int n_in,
                              void* d_out, int out_size) {
    const float* xyz   = (const float*)d_in[0];
    const int*   bound = (const int*)d_in[1];
    const float* Lg    = (const float*)d_in[2];
    const float* Hp    = (const float*)d_in[3];
    float* out = (float*)d_out;

    int N = in_sizes[0] / 3;

    const int VG = LRES * LRES * LRES;              // threads = VG/4
    transpose_grid_kernel<<<(VG / 4 + 255) / 256, 256>>>(Lg);

    const int VP = 3 * HRES * HRES;                 // threads = VP/4
    transpose_planes_kernel<<<(VP / 4 + 255) / 256, 256>>>(Hp);

    int threads = 2 * N;                            // 2 lanes per point
    gather_kernel<<<(threads + 255) / 256, 256>>>(xyz, bound, out, N);
}

// round 8
// speedup vs baseline: 2.0706x; 1.0260x over previous
#include <cuda_runtime.h>
#include <cuda_fp16.h>
#include <cuda_bf16.h>

#define LRES 128
#define HRES 1024
#define NCH 8

// Channel-innermost fp16 scratch copies (allocation-free: __device__ globals).
// One texel = 8 halves = 16B = exactly one LDG.128.
__device__ __half g_grid_h[LRES * LRES * LRES * NCH];    // [z][y][x][c]  32 MB
__device__ __half g_planes_h[3 * HRES * HRES * NCH];     // [p][h][w][c]  48 MB

__device__ __forceinline__ uint4 pack8_half(float4 a, float4 b) {
    union { uint4 u; __half2 h[4]; } r;
    r.h[0] = __floats2half2_rn(a.x, a.y);
    r.h[1] = __floats2half2_rn(a.z, a.w);
    r.h[2] = __floats2half2_rn(b.x, b.y);
    r.h[3] = __floats2half2_rn(b.z, b.w);
    return r.u;
}

// ---------------------------------------------------------------------------
// Fused transpose (R4-style 1 texel/thread, low regs, BW-bound):
//   threads [0, VG)            : grid  [C,D,H,W] fp32 -> [D,H,W,C] fp16
//   threads [VG, VG + 3*V2)    : planes [3,C,H,W] fp32 -> [3][H][W][C] fp16
// ---------------------------------------------------------------------------
__global__ void __launch_bounds__(256) transpose_all_kernel(
    const float* __restrict__ grid_in,
    const float* __restrict__ planes_in)
{
    const int VG = LRES * LRES * LRES;
    const int V2 = HRES * HRES;
    int t = blockIdx.x * blockDim.x + threadIdx.x;

    if (t < VG) {
        int v = t;
        float4 a, b;
        a.x = __ldg(grid_in + 0 * VG + v);
        a.y = __ldg(grid_in + 1 * VG + v);
        a.z = __ldg(grid_in + 2 * VG + v);
        a.w = __ldg(grid_in + 3 * VG + v);
        b.x = __ldg(grid_in + 4 * VG + v);
        b.y = __ldg(grid_in + 5 * VG + v);
        b.z = __ldg(grid_in + 6 * VG + v);
        b.w = __ldg(grid_in + 7 * VG + v);
        reinterpret_cast<uint4*>(g_grid_h)[v] = pack8_half(a, b);
    } else {
        int u = t - VG;
        if (u >= 3 * V2) return;
        int p = u / V2;
        int v = u - p * V2;
        const float* base = planes_in + (size_t)p * NCH * V2 + v;
        float4 a, b;
        a.x = __ldg(base + 0 * V2);
        a.y = __ldg(base + 1 * V2);
        a.z = __ldg(base + 2 * V2);
        a.w = __ldg(base + 3 * V2);
        b.x = __ldg(base + 4 * V2);
        b.y = __ldg(base + 5 * V2);
        b.z = __ldg(base + 6 * V2);
        b.w = __ldg(base + 7 * V2);
        reinterpret_cast<uint4*>(g_planes_h)[u] = pack8_half(a, b);
    }
}

// ---------------------------------------------------------------------------
// Pair-lane gather: lanes (2i, 2i+1) share point i; lane r handles the
// W-dimension index x_r of every sample pair. 10 LDG.128 per lane,
// half-exchange via 4 SHFL.BFLY, contiguous 16B store per lane.
// ---------------------------------------------------------------------------
__device__ __forceinline__ void to_idx(float c, int size, int& i0, int& i1, float& w) {
    // align_corners=True mapping; w from UNCLIPPED floor (matches ref).
    float p = (c + 1.0f) * 0.5f * (float)(size - 1);
    float f = floorf(p);
    w = p - f;
    int i = (int)f;
    i0 = min(max(i, 0), size - 1);
    i1 = min(i0 + 1, size - 1);
}

__device__ __forceinline__ void acc_texel(float* acc, uint4 v, float w) {
    union { uint4 u; __half2 h[4]; } r; r.u = v;
    float2 f0 = __half22float2(r.h[0]);
    float2 f1 = __half22float2(r.h[1]);
    float2 f2 = __half22float2(r.h[2]);
    float2 f3 = __half22float2(r.h[3]);
    acc[0] = fmaf(w, f0.x, acc[0]); acc[1] = fmaf(w, f0.y, acc[1]);
    acc[2] = fmaf(w, f1.x, acc[2]); acc[3] = fmaf(w, f1.y, acc[3]);
    acc[4] = fmaf(w, f2.x, acc[4]); acc[5] = fmaf(w, f2.y, acc[5]);
    acc[6] = fmaf(w, f3.x, acc[6]); acc[7] = fmaf(w, f3.y, acc[7]);
}

__global__ void __launch_bounds__(256) gather_kernel(
    const float* __restrict__ xyz,
    const int* __restrict__ bound_p,
    float* __restrict__ out,
    int N)
{
    int tid = blockIdx.x * blockDim.x + threadIdx.x;
    int n = tid >> 1;            // point index (2 lanes per point)
    int r = tid & 1;             // 0: low W index, 1: high W index
    if (n >= N) return;          // pairs drop together; warp stays pair-aligned

    int bi = __ldg(bound_p);
    float bound = (bi > 0 && bi < 100000000) ? (float)bi : __int_as_float(bi);
    float inv = 1.0f / bound;

    float x = __ldg(xyz + 3 * n + 0) * inv;
    float y = __ldg(xyz + 3 * n + 1) * inv;
    float z = __ldg(xyz + 3 * n + 2) * inv;

    const uint4* GT = reinterpret_cast<const uint4*>(g_grid_h);
    const uint4* PT = reinterpret_cast<const uint4*>(g_planes_h);

    // ---- index math (both lanes compute identically) ----
    int x0, x1, y0, y1, z0, z1;
    float wx, wy, wz;
    to_idx(x, LRES, x0, x1, wx);
    to_idx(y, LRES, y0, y1, wy);
    to_idx(z, LRES, z0, z1, wz);

    int xh0, xh1, yh0, yh1, zh0, zh1;
    float wxh, wyh, wzh;
    to_idx(x, HRES, xh0, xh1, wxh);
    to_idx(y, HRES, yh0, yh1, wyh);
    to_idx(z, HRES, zh0, zh1, wzh);

    // lane-specific W-dim picks + weights
    int   gx  = r ? x1  : x0;   float wgx = r ? wx  : 1.0f - wx;
    int   p0x = r ? xh1 : xh0;  float w0x = r ? wxh : 1.0f - wxh;  // plane0 W = x
    int   p1y = r ? yh1 : yh0;  float w1y = r ? wyh : 1.0f - wyh;  // plane1 W = y
    int   p2z = r ? zh1 : zh0;  float w2z = r ? wzh : 1.0f - wzh;  // plane2 W = z

    // ---- 10 loads, batched for MLP ----
    #define GIDX(zz, yy) (((zz) * LRES + (yy)) * LRES + gx)
    uint4 g00 = __ldg(GT + GIDX(z0, y0));
    uint4 g01 = __ldg(GT + GIDX(z0, y1));
    uint4 g10 = __ldg(GT + GIDX(z1, y0));
    uint4 g11 = __ldg(GT + GIDX(z1, y1));
    #undef GIDX
    #define PIDX(p, hh, ww) ((p) * (HRES * HRES) + (hh) * HRES + (ww))
    uint4 pa0 = __ldg(PT + PIDX(0, yh0, p0x));
    uint4 pa1 = __ldg(PT + PIDX(0, yh1, p0x));
    uint4 pb0 = __ldg(PT + PIDX(1, zh0, p1y));
    uint4 pb1 = __ldg(PT + PIDX(1, zh1, p1y));
    uint4 pc0 = __ldg(PT + PIDX(2, xh0, p2z));
    uint4 pc1 = __ldg(PT + PIDX(2, xh1, p2z));
    #undef PIDX

    // ---- accumulate fp32 (half the corners; pair exchange completes it) ----
    float acc[NCH];
#pragma unroll
    for (int c = 0; c < NCH; c++) acc[c] = 0.0f;

    {
        float uy = 1.0f - wy, uz = 1.0f - wz;
        acc_texel(acc, g00, uz * uy * wgx);
        acc_texel(acc, g01, uz * wy * wgx);
        acc_texel(acc, g10, wz * uy * wgx);
        acc_texel(acc, g11, wz * wy * wgx);
    }
    acc_texel(acc, pa0, (1.0f - wyh) * w0x);   // plane0: H = y
    acc_texel(acc, pa1, wyh * w0x);
    acc_texel(acc, pb0, (1.0f - wzh) * w1y);   // plane1: H = z
    acc_texel(acc, pb1, wzh * w1y);
    acc_texel(acc, pc0, (1.0f - wxh) * w2z);   // plane2: H = x
    acc_texel(acc, pc1, wxh * w2z);

    // ---- half exchange: 4 SHFLs instead of 8.
    // Lane 0 keeps channels 0..3 and needs partner's partial of 0..3;
    // lane 1 keeps channels 4..7 and needs partner's partial of 4..7.
    // So each lane SENDS the half it does NOT keep.
    unsigned mask = __activemask();
    float res[4];
#pragma unroll
    for (int c = 0; c < 4; c++) {
        float keep = r ? acc[c + 4] : acc[c];   // my partial of the half I store
        float send = r ? acc[c]     : acc[c + 4]; // partner's kept half, my partial
        float recv = __shfl_xor_sync(mask, send, 1);
        res[c] = keep + recv;
    }

    // ---- store: lane r writes float4 #r of point n -> fully contiguous ----
    reinterpret_cast<float4*>(out)[(size_t)n * 2 + r] =
        make_float4(res[0], res[1], res[2], res[3]);
}

extern "C" void kernel_launch(void* const* d_in, const int* in_sizes, int n_in,
                              void* d_out, int out_size) {
    const float* xyz   = (const float*)d_in[0];
    const int*   bound = (const int*)d_in[1];
    const float* Lg    = (const float*)d_in[2];
    const float* Hp    = (const float*)d_in[3];
    float* out = (float*)d_out;

    int N = in_sizes[0] / 3;

    const int VG = LRES * LRES * LRES;
    const int VT = VG + 3 * HRES * HRES;            // total transpose threads
    transpose_all_kernel<<<(VT + 255) / 256, 256>>>(Lg, Hp);

    int threads = 2 * N;                            // 2 lanes per point
    gather_kernel<<<(threads + 255) / 256, 256>>>(xyz, bound, out, N);
}